// round 1
// baseline (speedup 1.0000x reference)
#include <cuda_runtime.h>
#include <cstdint>

#define BB    4
#define LL    1024
#define DIMM  512
#define NH    8
#define HDIM  64
#define KNEED 716          // max(1, int(1024 * 0.7))
#define NEGV  (-1e9f)

// ---------------- scratch (static device globals; no allocation) ----------------
__device__ float g_q [BB*NH*LL*HDIM];   // (b,h,i,d)
__device__ float g_kt[BB*NH*HDIM*LL];   // (b,h,d,j)  transposed K
__device__ float g_v [BB*NH*LL*HDIM];   // (b,h,j,d)
__device__ float g_ao[BB*LL*DIMM];      // (b,i,h*64+d) attention output
__device__ float g_pw[BB*3];            // pattern weights per batch

// ======================= K1: QKV GEMM  (C = x @ Wqkv^T, scatter) =======================
__global__ void __launch_bounds__(256) qkv_gemm(const float* __restrict__ x,
                                                const float* __restrict__ W) {
    __shared__ float As[16][64];
    __shared__ float Bs[16][64];
    const int m0 = blockIdx.y * 64, n0 = blockIdx.x * 64;
    const int tid = threadIdx.x;
    const int ty = tid >> 4, tx = tid & 15;
    float acc[4][4] = {};
    for (int k0 = 0; k0 < 512; k0 += 16) {
        {
            int r = tid >> 2, kq = (tid & 3) * 4;
            float4 a = *(const float4*)(x + (size_t)(m0 + r) * 512 + k0 + kq);
            As[kq+0][r] = a.x; As[kq+1][r] = a.y; As[kq+2][r] = a.z; As[kq+3][r] = a.w;
            float4 b4 = *(const float4*)(W + (size_t)(n0 + r) * 512 + k0 + kq);
            Bs[kq+0][r] = b4.x; Bs[kq+1][r] = b4.y; Bs[kq+2][r] = b4.z; Bs[kq+3][r] = b4.w;
        }
        __syncthreads();
        #pragma unroll
        for (int kk = 0; kk < 16; kk++) {
            float4 av = *(const float4*)&As[kk][ty * 4];
            float4 bv = *(const float4*)&Bs[kk][tx * 4];
            float am[4] = {av.x, av.y, av.z, av.w};
            float bm[4] = {bv.x, bv.y, bv.z, bv.w};
            #pragma unroll
            for (int r = 0; r < 4; r++)
                #pragma unroll
                for (int c = 0; c < 4; c++)
                    acc[r][c] = fmaf(am[r], bm[c], acc[r][c]);
        }
        __syncthreads();
    }
    #pragma unroll
    for (int r = 0; r < 4; r++) {
        int m = m0 + ty * 4 + r;
        int b = m >> 10, i = m & 1023;
        #pragma unroll
        for (int c = 0; c < 4; c++) {
            int n = n0 + tx * 4 + c;
            float v = acc[r][c];
            if (n < 512) {
                int h = n >> 6, d = n & 63;
                g_q[(((size_t)(b * 8 + h) << 10) + i) * 64 + d] = v;
            } else if (n < 1024) {
                int nn = n - 512, h = nn >> 6, d = nn & 63;
                g_kt[((size_t)(b * 8 + h) * 64 + d) * 1024 + i] = v;
            } else {
                int nn = n - 1024, h = nn >> 6, d = nn & 63;
                g_v[(((size_t)(b * 8 + h) << 10) + i) * 64 + d] = v;
            }
        }
    }
}

// ======================= K2: pattern selector MLP =======================
__global__ void __launch_bounds__(512) selector(const float* __restrict__ x,
                                                const float* __restrict__ W1,
                                                const float* __restrict__ b1,
                                                const float* __restrict__ W2,
                                                const float* __restrict__ b2,
                                                const float* __restrict__ logtau) {
    __shared__ float pooled[512];
    __shared__ float hh[256];
    __shared__ float lg[3];
    const int b = blockIdx.x, tid = threadIdx.x;
    const float* xb = x + (size_t)b * 1024 * 512;
    float s = 0.f;
    #pragma unroll 4
    for (int i = 0; i < 1024; i++) s += xb[(size_t)i * 512 + tid];
    pooled[tid] = s * (1.0f / 1024.0f);
    __syncthreads();
    if (tid < 256) {
        float a = b1[tid];
        const float* wr = W1 + (size_t)tid * 512;
        #pragma unroll 4
        for (int d = 0; d < 512; d++) a = fmaf(pooled[d], wr[d], a);
        hh[tid] = a > 0.f ? a : 0.f;
    }
    __syncthreads();
    if (tid < 3) {
        float a = b2[tid];
        const float* wr = W2 + (size_t)tid * 256;
        for (int d = 0; d < 256; d++) a = fmaf(hh[d], wr[d], a);
        lg[tid] = a;
    }
    __syncthreads();
    if (tid == 0) {
        float tau = expf(logtau[0]);
        tau = fminf(fmaxf(tau, 1e-4f), 10.0f);
        float l0 = lg[0] / tau, l1 = lg[1] / tau, l2 = lg[2] / tau;
        float mx = fmaxf(l0, fmaxf(l1, l2));
        float e0 = expf(l0 - mx), e1 = expf(l1 - mx), e2 = expf(l2 - mx);
        float inv = 1.0f / (e0 + e1 + e2);
        g_pw[b * 3 + 0] = e0 * inv;
        g_pw[b * 3 + 1] = e1 * inv;
        g_pw[b * 3 + 2] = e2 * inv;
    }
}

// ======================= K3: fused attention =======================
struct SmemAttn {
    float  q[16][64];          // 4 KB
    float  sc[16][1024];       // 64 KB score/prob tile
    union {
        float4   chunk[2048];  // 32 KB  (K chunk [64][32]f4 / V chunk [128][16]f4)
        unsigned hist[8][256]; // 8 KB warp-private histograms
    } u;
    unsigned thr[16];
    float    rowmax[16];
    float    rowsum[16];
    int      anyf[16];
};

__device__ __forceinline__ unsigned ordkey(float s) {
    unsigned u = __float_as_uint(s);
    return (u & 0x80000000u) ? ~u : (u | 0x80000000u);
}

__global__ void __launch_bounds__(256) attn_kernel(const int* __restrict__ mask,
                                                   const float* __restrict__ sparse_w,
                                                   const float* __restrict__ sparse_b) {
    extern __shared__ char smraw[];
    SmemAttn* sm = (SmemAttn*)smraw;
    const int tid = threadIdx.x;
    const int i0 = blockIdx.x * 16;
    const int h  = blockIdx.y;
    const int b  = blockIdx.z;
    const int bh = b * 8 + h;
    const float* qg  = g_q  + (size_t)bh * 1024 * 64;
    const float* ktg = g_kt + (size_t)bh * 64 * 1024;
    const float* vg  = g_v  + (size_t)bh * 1024 * 64;

    const float pw0 = g_pw[b * 3 + 0], pw1 = g_pw[b * 3 + 1], pw2 = g_pw[b * 3 + 2];
    const float wsp = sparse_w[h], bsp = sparse_b[h];

    // ---- load q tile ----
    for (int idx = tid; idx < 16 * 64; idx += 256) {
        int r = idx >> 6, d = idx & 63;
        sm->q[r][d] = qg[(size_t)(i0 + r) * 64 + d];
    }

    // ---- phase 1: scores (16 rows x 1024 cols) ----
    const int rg = tid >> 5;   // 0..7 -> rows rg*2, rg*2+1
    const int cg = tid & 31;   // 0..31 -> 4 cols each
    const float scale = 0.125f;
    for (int j0 = 0; j0 < 1024; j0 += 128) {
        __syncthreads();
        for (int idx = tid; idx < 64 * 32; idx += 256) {
            int d = idx >> 5, jv = idx & 31;
            sm->u.chunk[idx] = *(const float4*)(ktg + (size_t)d * 1024 + j0 + jv * 4);
        }
        __syncthreads();
        float4 a0 = {0, 0, 0, 0}, a1 = {0, 0, 0, 0};
        #pragma unroll
        for (int d = 0; d < 64; d++) {
            float q0 = sm->q[rg * 2][d];
            float q1 = sm->q[rg * 2 + 1][d];
            float4 kv = sm->u.chunk[d * 32 + cg];
            a0.x = fmaf(q0, kv.x, a0.x); a0.y = fmaf(q0, kv.y, a0.y);
            a0.z = fmaf(q0, kv.z, a0.z); a0.w = fmaf(q0, kv.w, a0.w);
            a1.x = fmaf(q1, kv.x, a1.x); a1.y = fmaf(q1, kv.y, a1.y);
            a1.z = fmaf(q1, kv.z, a1.z); a1.w = fmaf(q1, kv.w, a1.w);
        }
        a0.x *= scale; a0.y *= scale; a0.z *= scale; a0.w *= scale;
        a1.x *= scale; a1.y *= scale; a1.z *= scale; a1.w *= scale;
        *(float4*)&sm->sc[rg * 2][j0 + cg * 4]     = a0;
        *(float4*)&sm->sc[rg * 2 + 1][j0 + cg * 4] = a1;
    }
    __syncthreads();

    // ---- phase 2: exact kth-largest (716 of 1024) per row via radix select ----
    // warp w handles rows 2w, 2w+1 with a private histogram (match_any-aggregated)
    {
        const int wq = tid >> 5, lane = tid & 31;
        for (int rr = 0; rr < 2; rr++) {
            const int r = wq * 2 + rr;
            unsigned prefix = 0;
            int kneed = KNEED;
            #pragma unroll
            for (int pass = 0; pass < 4; pass++) {
                const int shift = 24 - 8 * pass;
                #pragma unroll
                for (int q = 0; q < 8; q++) sm->u.hist[wq][lane * 8 + q] = 0u;
                __syncwarp();
                for (int t = 0; t < 32; t++) {
                    int j = lane + t * 32;
                    float s = fmaf(sm->sc[r][j], wsp, bsp);
                    unsigned u = ordkey(s);
                    bool cand;
                    if (pass == 0) cand = true;
                    else           cand = (((u ^ prefix) >> (shift + 8)) == 0u);
                    int bucket = cand ? (int)((u >> shift) & 255u) : 256;
                    unsigned mm = __match_any_sync(0xffffffffu, bucket);
                    if ((__ffs(mm) - 1) == lane && bucket < 256)
                        atomicAdd(&sm->u.hist[wq][bucket], (unsigned)__popc(mm));
                }
                __syncwarp();
                const int base = 255 - lane * 8;
                int c[8]; int loc = 0;
                #pragma unroll
                for (int q = 0; q < 8; q++) { c[q] = (int)sm->u.hist[wq][base - q]; loc += c[q]; }
                int pre = loc;
                #pragma unroll
                for (int o = 1; o < 32; o <<= 1) {
                    int v = __shfl_up_sync(0xffffffffu, pre, o);
                    if (lane >= o) pre += v;
                }
                const int excl = pre - loc;
                const bool hit = (excl < kneed) && (kneed <= pre);
                const unsigned hb = __ballot_sync(0xffffffffu, hit);
                const int hl = __ffs(hb) - 1;
                int bsel = 0, kn2 = 0;
                if (hit) {
                    int rem = kneed - excl;
                    #pragma unroll
                    for (int q = 0; q < 8; q++) {
                        if (rem <= c[q]) { bsel = base - q; kn2 = rem; break; }
                        rem -= c[q];
                    }
                }
                bsel = __shfl_sync(0xffffffffu, bsel, hl);
                kn2  = __shfl_sync(0xffffffffu, kn2,  hl);
                prefix |= ((unsigned)bsel) << shift;
                kneed = kn2;
                __syncwarp();
            }
            if (lane == 0) sm->thr[r] = prefix;
        }
    }
    __syncthreads();

    // ---- phase 3: combined mask + fallback + softmax ----
    const int r3 = tid >> 4;   // 16 threads per row
    const int c3 = tid & 15;
    {
        const int* mrow = mask + b * 1024;
        const unsigned thrv = sm->thr[r3];
        const int ii = i0 + r3;
        float locmax = -3.0e38f;
        int any = 0;
        for (int t = 0; t < 64; t++) {
            int j = c3 + t * 16;
            float f = sm->sc[r3][j];
            float s = fmaf(f, wsp, bsp);
            float smv = (ordkey(s) >= thrv) ? 1.0f : 0.0f;
            float lcl = (j >= ii - 16 && j <= ii + 16) ? 1.0f : 0.0f;
            float comb = fmaf(pw0, lcl, fmaf(pw2, smv, pw1));
            bool keep = (comb > 0.05f) && (mrow[j] != 0);
            float val = keep ? f : NEGV;
            sm->sc[r3][j] = val;
            if (keep) { locmax = fmaxf(locmax, f); any = 1; }
        }
        #pragma unroll
        for (int o = 8; o; o >>= 1) {
            locmax = fmaxf(locmax, __shfl_down_sync(0xffffffffu, locmax, o, 16));
            any   |= __shfl_down_sync(0xffffffffu, any, o, 16);
        }
        if (c3 == 0) { sm->rowmax[r3] = locmax; sm->anyf[r3] = any; }
    }
    __syncthreads();
    if (tid < 16) {
        if (!sm->anyf[tid]) { sm->sc[tid][0] = 0.0f; sm->rowmax[tid] = 0.0f; }
    }
    __syncthreads();
    {
        const float rmax = sm->rowmax[r3];
        float lsum = 0.f;
        for (int t = 0; t < 64; t++) {
            int j = c3 + t * 16;
            float e = __expf(sm->sc[r3][j] - rmax);
            sm->sc[r3][j] = e;
            lsum += e;
        }
        #pragma unroll
        for (int o = 8; o; o >>= 1)
            lsum += __shfl_down_sync(0xffffffffu, lsum, o, 16);
        if (c3 == 0) sm->rowsum[r3] = lsum;
    }

    // ---- phase 4: AV  (out[r][d] = sum_j p[r][j] * v[j][d]) ----
    float4 acc = {0, 0, 0, 0};
    for (int j0 = 0; j0 < 1024; j0 += 128) {
        __syncthreads();
        for (int idx = tid; idx < 128 * 16; idx += 256) {
            int jj = idx >> 4, dg = idx & 15;
            sm->u.chunk[idx] = *(const float4*)(vg + (size_t)(j0 + jj) * 64 + dg * 4);
        }
        __syncthreads();
        #pragma unroll 4
        for (int jj = 0; jj < 128; jj++) {
            float p = sm->sc[r3][j0 + jj];
            float4 vv = sm->u.chunk[jj * 16 + c3];
            acc.x = fmaf(p, vv.x, acc.x); acc.y = fmaf(p, vv.y, acc.y);
            acc.z = fmaf(p, vv.z, acc.z); acc.w = fmaf(p, vv.w, acc.w);
        }
    }
    const float inv = 1.0f / sm->rowsum[r3];
    acc.x *= inv; acc.y *= inv; acc.z *= inv; acc.w *= inv;
    *(float4*)(g_ao + ((size_t)(b * 1024 + i0 + r3)) * 512 + h * 64 + c3 * 4) = acc;
}

// ======================= K4: output projection =======================
__global__ void __launch_bounds__(256) proj_gemm(const float* __restrict__ W,
                                                 const float* __restrict__ bias,
                                                 float* __restrict__ out) {
    __shared__ float As[16][64];
    __shared__ float Bs[16][64];
    const int m0 = blockIdx.y * 64, n0 = blockIdx.x * 64;
    const int tid = threadIdx.x;
    const int ty = tid >> 4, tx = tid & 15;
    float acc[4][4] = {};
    for (int k0 = 0; k0 < 512; k0 += 16) {
        {
            int r = tid >> 2, kq = (tid & 3) * 4;
            float4 a = *(const float4*)(g_ao + (size_t)(m0 + r) * 512 + k0 + kq);
            As[kq+0][r] = a.x; As[kq+1][r] = a.y; As[kq+2][r] = a.z; As[kq+3][r] = a.w;
            float4 b4 = *(const float4*)(W + (size_t)(n0 + r) * 512 + k0 + kq);
            Bs[kq+0][r] = b4.x; Bs[kq+1][r] = b4.y; Bs[kq+2][r] = b4.z; Bs[kq+3][r] = b4.w;
        }
        __syncthreads();
        #pragma unroll
        for (int kk = 0; kk < 16; kk++) {
            float4 av = *(const float4*)&As[kk][ty * 4];
            float4 bv = *(const float4*)&Bs[kk][tx * 4];
            float am[4] = {av.x, av.y, av.z, av.w};
            float bm[4] = {bv.x, bv.y, bv.z, bv.w};
            #pragma unroll
            for (int r = 0; r < 4; r++)
                #pragma unroll
                for (int c = 0; c < 4; c++)
                    acc[r][c] = fmaf(am[r], bm[c], acc[r][c]);
        }
        __syncthreads();
    }
    #pragma unroll
    for (int r = 0; r < 4; r++) {
        int m = m0 + ty * 4 + r;
        #pragma unroll
        for (int c = 0; c < 4; c++) {
            int n = n0 + tx * 4 + c;
            out[(size_t)m * 512 + n] = acc[r][c] + bias[n];
        }
    }
}

// ======================= launch =======================
extern "C" void kernel_launch(void* const* d_in, const int* in_sizes, int n_in,
                              void* d_out, int out_size) {
    const float* x      = (const float*)d_in[0];
    const int*   mask   = (const int*)  d_in[1];
    const float* Wqkv   = (const float*)d_in[2];
    const float* Wproj  = (const float*)d_in[3];
    const float* bproj  = (const float*)d_in[4];
    const float* Wsel1  = (const float*)d_in[5];
    const float* bsel1  = (const float*)d_in[6];
    const float* Wsel2  = (const float*)d_in[7];
    const float* bsel2  = (const float*)d_in[8];
    const float* logtau = (const float*)d_in[9];
    const float* sw     = (const float*)d_in[10];
    const float* sb     = (const float*)d_in[11];
    float* out = (float*)d_out;

    cudaFuncSetAttribute(attn_kernel, cudaFuncAttributeMaxDynamicSharedMemorySize,
                         (int)sizeof(SmemAttn));

    qkv_gemm<<<dim3(24, 64), 256>>>(x, Wqkv);
    selector<<<4, 512>>>(x, Wsel1, bsel1, Wsel2, bsel2, logtau);
    attn_kernel<<<dim3(64, 8, 4), 256, sizeof(SmemAttn)>>>(mask, sw, sb);
    proj_gemm<<<dim3(8, 64), 256>>>(Wproj, bproj, out);
}

// round 3
// speedup vs baseline: 1.3896x; 1.3896x over previous
#include <cuda_runtime.h>
#include <cstdint>

#define BB    4
#define LL    1024
#define DIMM  512
#define NH    8
#define HDIM  64
#define KNEED 716          // max(1, int(1024 * 0.7))
#define NEGV  (-1e9f)

typedef unsigned long long ull;

// ---------------- scratch (static device globals; no allocation) ----------------
__device__ float g_q [BB*NH*LL*HDIM];   // (b,h,i,d)
__device__ float g_kt[BB*NH*HDIM*LL];   // (b,h,d,j)  transposed K
__device__ float g_v [BB*NH*LL*HDIM];   // (b,h,j,d)
__device__ float g_ao[BB*LL*DIMM];      // (b,i,h*64+d) attention output
__device__ float g_pw[BB*3];            // pattern weights per batch
__device__ float g_part[BB*8*DIMM];     // pooling partials

// ---------------- f32x2 packed helpers ----------------
__device__ __forceinline__ ull pk2(float a, float b) {
    ull r; asm("mov.b64 %0,{%1,%2};" : "=l"(r) : "f"(a), "f"(b)); return r;
}
__device__ __forceinline__ void fma2(ull& d, ull a, ull b) {
    asm("fma.rn.f32x2 %0, %1, %2, %0;" : "+l"(d) : "l"(a), "l"(b));
}
__device__ __forceinline__ ull mul2(ull a, ull b) {
    ull r; asm("mul.rn.f32x2 %0, %1, %2;" : "=l"(r) : "l"(a), "l"(b)); return r;
}
__device__ __forceinline__ ull add2(ull a, ull b) {
    ull r; asm("add.rn.f32x2 %0, %1, %2;" : "=l"(r) : "l"(a), "l"(b)); return r;
}
__device__ __forceinline__ float2 upk(ull v) {
    float2 r; asm("mov.b64 {%0,%1},%2;" : "=f"(r.x), "=f"(r.y) : "l"(v)); return r;
}
__device__ __forceinline__ unsigned ordkey(float s) {
    unsigned u = __float_as_uint(s);
    return (u & 0x80000000u) ? ~u : (u | 0x80000000u);
}

// ======================= K1: 128x128x16 GEMM, f32x2, MODE 0=qkv scatter, 1=proj =======================
// NOTE: smem row pad = 132 floats (528 B = 33*16) so 16-byte vector loads from
// any row are aligned. (130 -> 520 B broke alignment on odd rows: R2 trap.)
template<int MODE>
__global__ void __launch_bounds__(256) gemm128(const float* __restrict__ A,
                                               const float* __restrict__ W,
                                               const float* __restrict__ bias,
                                               float* __restrict__ out) {
    __shared__ float As[16][132];
    __shared__ float Bs[16][132];
    const int m0 = blockIdx.y * 128, n0 = blockIdx.x * 128;
    const int tid = threadIdx.x;
    const int tx = tid & 15, ty = tid >> 4;
    const float* Ap = (MODE == 1) ? g_ao : A;

    ull acc[8][4];
    #pragma unroll
    for (int r = 0; r < 8; r++)
        #pragma unroll
        for (int c = 0; c < 4; c++) acc[r][c] = 0ull;

    // prefetch first tile
    float4 pa[2], pb[2];
    #pragma unroll
    for (int i = 0; i < 2; i++) {
        int idx = tid + i * 256;
        int r = idx >> 2, kq = (idx & 3) * 4;
        pa[i] = *(const float4*)(Ap + (size_t)(m0 + r) * 512 + kq);
        pb[i] = *(const float4*)(W  + (size_t)(n0 + r) * 512 + kq);
    }

    for (int k0 = 0; k0 < 512; k0 += 16) {
        #pragma unroll
        for (int i = 0; i < 2; i++) {
            int idx = tid + i * 256;
            int r = idx >> 2, kq = (idx & 3) * 4;
            As[kq+0][r] = pa[i].x; As[kq+1][r] = pa[i].y; As[kq+2][r] = pa[i].z; As[kq+3][r] = pa[i].w;
            Bs[kq+0][r] = pb[i].x; Bs[kq+1][r] = pb[i].y; Bs[kq+2][r] = pb[i].z; Bs[kq+3][r] = pb[i].w;
        }
        __syncthreads();
        if (k0 + 16 < 512) {
            #pragma unroll
            for (int i = 0; i < 2; i++) {
                int idx = tid + i * 256;
                int r = idx >> 2, kq = (idx & 3) * 4;
                pa[i] = *(const float4*)(Ap + (size_t)(m0 + r) * 512 + k0 + 16 + kq);
                pb[i] = *(const float4*)(W  + (size_t)(n0 + r) * 512 + k0 + 16 + kq);
            }
        }
        #pragma unroll
        for (int kk = 0; kk < 16; kk++) {
            ull kp[4];
            {
                ulonglong2 kA = *(const ulonglong2*)&Bs[kk][tx * 8];
                ulonglong2 kB = *(const ulonglong2*)&Bs[kk][tx * 8 + 4];
                kp[0] = kA.x; kp[1] = kA.y; kp[2] = kB.x; kp[3] = kB.y;
            }
            ull ab[8];
            #pragma unroll
            for (int r = 0; r < 8; r++) {
                float a = As[kk][ty * 8 + r];
                ab[r] = pk2(a, a);
            }
            #pragma unroll
            for (int r = 0; r < 8; r++)
                #pragma unroll
                for (int c = 0; c < 4; c++)
                    fma2(acc[r][c], ab[r], kp[c]);
        }
        __syncthreads();
    }

    #pragma unroll
    for (int r = 0; r < 8; r++) {
        int m = m0 + ty * 8 + r;
        if (MODE == 0) {
            int b = m >> 10, i = m & 1023;
            #pragma unroll
            for (int c = 0; c < 4; c++) {
                int n = n0 + tx * 8 + 2 * c;
                float2 v = upk(acc[r][c]);
                if (n < 512) {
                    int h = n >> 6, d = n & 63;
                    float* p = g_q + (((size_t)(b * 8 + h) << 10) + i) * 64 + d;
                    p[0] = v.x; p[1] = v.y;
                } else if (n < 1024) {
                    int nn = n - 512, h = nn >> 6, d = nn & 63;
                    float* p = g_kt + ((size_t)(b * 8 + h) * 64 + d) * 1024 + i;
                    p[0] = v.x; p[1024] = v.y;
                } else {
                    int nn = n - 1024, h = nn >> 6, d = nn & 63;
                    float* p = g_v + (((size_t)(b * 8 + h) << 10) + i) * 64 + d;
                    p[0] = v.x; p[1] = v.y;
                }
            }
        } else {
            #pragma unroll
            for (int c = 0; c < 4; c++) {
                int n = n0 + tx * 8 + 2 * c;
                ull bv = *(const ull*)(bias + n);
                *(ull*)(out + (size_t)m * 512 + n) = add2(acc[r][c], bv);
            }
        }
    }
}

// ======================= K2: pooling + selector =======================
__global__ void __launch_bounds__(512) pool_kernel(const float* __restrict__ x) {
    const int b = blockIdx.x >> 3, s = blockIdx.x & 7;
    const int tid = threadIdx.x;
    const float* xb = x + ((size_t)b * 1024 + s * 128) * 512;
    float sum = 0.f;
    #pragma unroll 4
    for (int i = 0; i < 128; i++) sum += xb[(size_t)i * 512 + tid];
    g_part[(b * 8 + s) * 512 + tid] = sum;
}

__global__ void __launch_bounds__(512) selector(const float* __restrict__ W1,
                                                const float* __restrict__ b1,
                                                const float* __restrict__ W2,
                                                const float* __restrict__ b2,
                                                const float* __restrict__ logtau) {
    __shared__ float pooled[512];
    __shared__ float hh[256];
    __shared__ float lg[3];
    const int b = blockIdx.x, tid = threadIdx.x;
    {
        float s = 0.f;
        #pragma unroll
        for (int p = 0; p < 8; p++) s += g_part[(b * 8 + p) * 512 + tid];
        pooled[tid] = s * (1.0f / 1024.0f);
    }
    __syncthreads();
    if (tid < 256) {
        float a = b1[tid];
        const float* wr = W1 + (size_t)tid * 512;
        #pragma unroll 4
        for (int d = 0; d < 512; d++) a = fmaf(pooled[d], wr[d], a);
        hh[tid] = a > 0.f ? a : 0.f;
    }
    __syncthreads();
    if (tid < 3) {
        float a = b2[tid];
        const float* wr = W2 + (size_t)tid * 256;
        for (int d = 0; d < 256; d++) a = fmaf(hh[d], wr[d], a);
        lg[tid] = a;
    }
    __syncthreads();
    if (tid == 0) {
        float tau = expf(logtau[0]);
        tau = fminf(fmaxf(tau, 1e-4f), 10.0f);
        float l0 = lg[0] / tau, l1 = lg[1] / tau, l2 = lg[2] / tau;
        float mx = fmaxf(l0, fmaxf(l1, l2));
        float e0 = expf(l0 - mx), e1 = expf(l1 - mx), e2 = expf(l2 - mx);
        float inv = 1.0f / (e0 + e1 + e2);
        g_pw[b * 3 + 0] = e0 * inv;
        g_pw[b * 3 + 1] = e1 * inv;
        g_pw[b * 3 + 2] = e2 * inv;
    }
}

// ======================= K3: fused attention (32 rows / block, 512 threads) =======================
struct SmemAttn {
    float qT[64][33];             // ~8.5 KB, qT[d][r] (scalar access only)
    float sc[32][1024];           // 128 KB (row stride 4096 B, 16B-aligned)
    union {
        float    kchunk[16][1024];   // 64 KB (row 4096 B)
        float    vchunk[128][64];    // 32 KB (row 256 B)
        unsigned hist[16][256];      // 16 KB
    } u;
    unsigned thr[32];
    float    rowmax[32];
    float    rowsum[32];
    int      anyf[32];
};

__global__ void __launch_bounds__(512) attn_kernel(const int* __restrict__ mask,
                                                   const float* __restrict__ sparse_w,
                                                   const float* __restrict__ sparse_b) {
    extern __shared__ char smraw[];
    SmemAttn* sm = (SmemAttn*)smraw;
    const int tid = threadIdx.x;
    const int i0 = blockIdx.x * 32;
    const int h  = blockIdx.y;
    const int b  = blockIdx.z;
    const int bh = b * 8 + h;
    const float* qg  = g_q  + (size_t)bh * 1024 * 64;
    const float* ktg = g_kt + (size_t)bh * 64 * 1024;
    const float* vg  = g_v  + (size_t)bh * 1024 * 64;

    const float pw0 = g_pw[b * 3 + 0], pw1 = g_pw[b * 3 + 1], pw2 = g_pw[b * 3 + 2];
    const float wsp = sparse_w[h], bsp = sparse_b[h];
    // does the sparse mask actually influence keep decisions?
    const bool need_smask = (((pw1 > 0.05f) != (pw1 + pw2 > 0.05f)) ||
                             ((pw0 + pw1 > 0.05f) != (pw0 + pw1 + pw2 > 0.05f)));

    // ---- load qT (transposed q tile) ----
    #pragma unroll
    for (int it = 0; it < 4; it++) {
        int idx = tid + it * 512;          // 0..2047
        int r = idx >> 6, d = idx & 63;
        sm->qT[d][r] = qg[(size_t)(i0 + r) * 64 + d];
    }

    // ---- phase 1: scores, 8x8 micro-tile, f32x2 ----
    const int rg = tid >> 7;     // 0..3 -> rows rg*8..+8
    const int cg = tid & 127;    // cols cg*8..+8
    ull acc[8][4];
    #pragma unroll
    for (int r = 0; r < 8; r++)
        #pragma unroll
        for (int c = 0; c < 4; c++) acc[r][c] = 0ull;

    for (int d0 = 0; d0 < 64; d0 += 16) {
        __syncthreads();
        #pragma unroll
        for (int it = 0; it < 8; it++) {
            int idx = tid + it * 512;      // 0..4095 float4 slots
            int d = idx >> 8, jf = (idx & 255) * 4;
            *(float4*)&sm->u.kchunk[d][jf] =
                *(const float4*)(ktg + (size_t)(d0 + d) * 1024 + jf);
        }
        __syncthreads();
        #pragma unroll
        for (int dd = 0; dd < 16; dd++) {
            ull kp[4];
            {
                ulonglong2 kA = *(const ulonglong2*)&sm->u.kchunk[dd][cg * 8];
                ulonglong2 kB = *(const ulonglong2*)&sm->u.kchunk[dd][cg * 8 + 4];
                kp[0] = kA.x; kp[1] = kA.y; kp[2] = kB.x; kp[3] = kB.y;
            }
            ull qb[8];
            #pragma unroll
            for (int r = 0; r < 8; r++) {
                float q = sm->qT[d0 + dd][rg * 8 + r];
                qb[r] = pk2(q, q);
            }
            #pragma unroll
            for (int r = 0; r < 8; r++)
                #pragma unroll
                for (int c = 0; c < 4; c++)
                    fma2(acc[r][c], qb[r], kp[c]);
        }
    }
    {
        const ull sc2 = pk2(0.125f, 0.125f);
        #pragma unroll
        for (int r = 0; r < 8; r++)
            #pragma unroll
            for (int c = 0; c < 4; c++)
                *(ull*)&sm->sc[rg * 8 + r][cg * 8 + 2 * c] = mul2(acc[r][c], sc2);
    }
    __syncthreads();

    // ---- phase 2: exact kth-largest per row (radix select), 16 warps x 2 rows ----
    if (need_smask) {
        const int wq = tid >> 5, lane = tid & 31;
        for (int rr = 0; rr < 2; rr++) {
            const int r = wq * 2 + rr;
            unsigned prefix = 0;
            int kneed = KNEED;
            #pragma unroll
            for (int pass = 0; pass < 4; pass++) {
                const int shift = 24 - 8 * pass;
                #pragma unroll
                for (int q = 0; q < 8; q++) sm->u.hist[wq][lane * 8 + q] = 0u;
                __syncwarp();
                for (int t = 0; t < 32; t++) {
                    int j = lane + t * 32;
                    float s = fmaf(sm->sc[r][j], wsp, bsp);
                    unsigned u = ordkey(s);
                    bool cand;
                    if (pass == 0) cand = true;
                    else           cand = (((u ^ prefix) >> (shift + 8)) == 0u);
                    int bucket = cand ? (int)((u >> shift) & 255u) : 256;
                    unsigned mm = __match_any_sync(0xffffffffu, bucket);
                    if ((__ffs(mm) - 1) == lane && bucket < 256)
                        atomicAdd(&sm->u.hist[wq][bucket], (unsigned)__popc(mm));
                }
                __syncwarp();
                const int base = 255 - lane * 8;
                int c[8]; int loc = 0;
                #pragma unroll
                for (int q = 0; q < 8; q++) { c[q] = (int)sm->u.hist[wq][base - q]; loc += c[q]; }
                int pre = loc;
                #pragma unroll
                for (int o = 1; o < 32; o <<= 1) {
                    int v = __shfl_up_sync(0xffffffffu, pre, o);
                    if (lane >= o) pre += v;
                }
                const int excl = pre - loc;
                const bool hit = (excl < kneed) && (kneed <= pre);
                const unsigned hb = __ballot_sync(0xffffffffu, hit);
                const int hl = __ffs(hb) - 1;
                int bsel = 0, kn2 = 0;
                if (hit) {
                    int rem = kneed - excl;
                    #pragma unroll
                    for (int q = 0; q < 8; q++) {
                        if (rem <= c[q]) { bsel = base - q; kn2 = rem; break; }
                        rem -= c[q];
                    }
                }
                bsel = __shfl_sync(0xffffffffu, bsel, hl);
                kn2  = __shfl_sync(0xffffffffu, kn2,  hl);
                prefix |= ((unsigned)bsel) << shift;
                kneed = kn2;
                __syncwarp();
            }
            if (lane == 0) sm->thr[r] = prefix;
        }
    } else {
        if (tid < 32) sm->thr[tid] = 0u;   // smv=1 everywhere; keep-decision unchanged
    }
    __syncthreads();

    // ---- phase 3: combined mask + fallback + softmax ----
    const int r3 = tid >> 4;   // 0..31
    const int c3 = tid & 15;
    {
        const int* mrow = mask + b * 1024;
        const unsigned thrv = sm->thr[r3];
        const int ii = i0 + r3;
        float locmax = -3.0e38f;
        int any = 0;
        for (int t = 0; t < 64; t++) {
            int j = c3 + t * 16;
            float f = sm->sc[r3][j];
            float s = fmaf(f, wsp, bsp);
            float smv = (ordkey(s) >= thrv) ? 1.0f : 0.0f;
            float lcl = (j >= ii - 16 && j <= ii + 16) ? 1.0f : 0.0f;
            float comb = fmaf(pw0, lcl, fmaf(pw2, smv, pw1));
            bool keep = (comb > 0.05f) && (mrow[j] != 0);
            float val = keep ? f : NEGV;
            sm->sc[r3][j] = val;
            if (keep) { locmax = fmaxf(locmax, f); any = 1; }
        }
        #pragma unroll
        for (int o = 8; o; o >>= 1) {
            locmax = fmaxf(locmax, __shfl_down_sync(0xffffffffu, locmax, o, 16));
            any   |= __shfl_down_sync(0xffffffffu, any, o, 16);
        }
        if (c3 == 0) { sm->rowmax[r3] = locmax; sm->anyf[r3] = any; }
    }
    __syncthreads();
    if (tid < 32) {
        if (!sm->anyf[tid]) { sm->sc[tid][0] = 0.0f; sm->rowmax[tid] = 0.0f; }
    }
    __syncthreads();
    {
        const float rmax = sm->rowmax[r3];
        float lsum = 0.f;
        for (int t = 0; t < 64; t++) {
            int j = c3 + t * 16;
            float e = __expf(sm->sc[r3][j] - rmax);
            sm->sc[r3][j] = e;
            lsum += e;
        }
        #pragma unroll
        for (int o = 8; o; o >>= 1)
            lsum += __shfl_down_sync(0xffffffffu, lsum, o, 16);
        if (c3 == 0) sm->rowsum[r3] = lsum;
    }

    // ---- phase 4: AV, 128 active threads, 2 rows x 8 cols each, f32x2 ----
    const int rg4 = tid >> 3;        // 0..15 (valid when tid<128), rows rg4*2..+2
    const int cg4 = tid & 7;         // cols cg4*8..+8
    ull a0[4] = {0,0,0,0}, a1[4] = {0,0,0,0};
    for (int j0 = 0; j0 < 1024; j0 += 128) {
        __syncthreads();
        #pragma unroll
        for (int it = 0; it < 4; it++) {
            int idx = tid + it * 512;      // 0..2047 float4 slots
            int jj = idx >> 4, df = (idx & 15) * 4;
            *(float4*)&sm->u.vchunk[jj][df] =
                *(const float4*)(vg + (size_t)(j0 + jj) * 64 + df);
        }
        __syncthreads();
        if (tid < 128) {
            const int r0 = rg4 * 2;
            #pragma unroll 4
            for (int jj = 0; jj < 128; jj++) {
                float p0 = sm->sc[r0][j0 + jj];
                float p1 = sm->sc[r0 + 1][j0 + jj];
                ull pb0 = pk2(p0, p0), pb1 = pk2(p1, p1);
                ulonglong2 vA = *(const ulonglong2*)&sm->u.vchunk[jj][cg4 * 8];
                ulonglong2 vB = *(const ulonglong2*)&sm->u.vchunk[jj][cg4 * 8 + 4];
                fma2(a0[0], pb0, vA.x); fma2(a0[1], pb0, vA.y);
                fma2(a0[2], pb0, vB.x); fma2(a0[3], pb0, vB.y);
                fma2(a1[0], pb1, vA.x); fma2(a1[1], pb1, vA.y);
                fma2(a1[2], pb1, vB.x); fma2(a1[3], pb1, vB.y);
            }
        }
    }
    if (tid < 128) {
        const int r0 = rg4 * 2;
        const float inv0 = 1.0f / sm->rowsum[r0];
        const float inv1 = 1.0f / sm->rowsum[r0 + 1];
        float* o0 = g_ao + ((size_t)(b * 1024 + i0 + r0)) * 512 + h * 64 + cg4 * 8;
        float* o1 = o0 + 512;
        #pragma unroll
        for (int c = 0; c < 4; c++) {
            float2 v0 = upk(a0[c]);
            o0[2*c] = v0.x * inv0; o0[2*c+1] = v0.y * inv0;
            float2 v1 = upk(a1[c]);
            o1[2*c] = v1.x * inv1; o1[2*c+1] = v1.y * inv1;
        }
    }
}

// ======================= launch =======================
extern "C" void kernel_launch(void* const* d_in, const int* in_sizes, int n_in,
                              void* d_out, int out_size) {
    const float* x      = (const float*)d_in[0];
    const int*   mask   = (const int*)  d_in[1];
    const float* Wqkv   = (const float*)d_in[2];
    const float* Wproj  = (const float*)d_in[3];
    const float* bproj  = (const float*)d_in[4];
    const float* Wsel1  = (const float*)d_in[5];
    const float* bsel1  = (const float*)d_in[6];
    const float* Wsel2  = (const float*)d_in[7];
    const float* bsel2  = (const float*)d_in[8];
    const float* logtau = (const float*)d_in[9];
    const float* sw     = (const float*)d_in[10];
    const float* sb     = (const float*)d_in[11];
    float* out = (float*)d_out;

    static int smem_set = 0;
    if (!smem_set) {
        cudaFuncSetAttribute(attn_kernel, cudaFuncAttributeMaxDynamicSharedMemorySize,
                             (int)sizeof(SmemAttn));
        smem_set = 1;
    }

    gemm128<0><<<dim3(12, 32), 256>>>(x, Wqkv, nullptr, nullptr);
    pool_kernel<<<32, 512>>>(x);
    selector<<<4, 512>>>(Wsel1, bsel1, Wsel2, bsel2, logtau);
    attn_kernel<<<dim3(32, 8, 4), 512, sizeof(SmemAttn)>>>(mask, sw, sb);
    gemm128<1><<<dim3(4, 32), 256>>>(nullptr, Wproj, bproj, out);
}

// round 4
// speedup vs baseline: 1.9766x; 1.4224x over previous
#include <cuda_runtime.h>
#include <cstdint>

#define BB    4
#define LL    1024
#define DIMM  512
#define NH    8
#define HDIM  64
#define KNEED 716          // max(1, int(1024 * 0.7))
#define NEGV  (-1e9f)

typedef unsigned long long ull;

// ---------------- scratch (static device globals; no allocation) ----------------
__device__ float g_q [BB*NH*LL*HDIM];   // (b,h,i,d)
__device__ float g_kt[BB*NH*HDIM*LL];   // (b,h,d,j)  transposed K
__device__ float g_v [BB*NH*LL*HDIM];   // (b,h,j,d)
__device__ float g_ao[BB*LL*DIMM];      // (b,i,h*64+d) attention output
__device__ float g_pw[BB*3];            // pattern weights per batch
__device__ float g_part[BB*8*DIMM];     // pooling partials

// ---------------- f32x2 packed helpers ----------------
__device__ __forceinline__ ull pk2(float a, float b) {
    ull r; asm("mov.b64 %0,{%1,%2};" : "=l"(r) : "f"(a), "f"(b)); return r;
}
__device__ __forceinline__ void fma2(ull& d, ull a, ull b) {
    asm("fma.rn.f32x2 %0, %1, %2, %0;" : "+l"(d) : "l"(a), "l"(b));
}
__device__ __forceinline__ ull mul2(ull a, ull b) {
    ull r; asm("mul.rn.f32x2 %0, %1, %2;" : "=l"(r) : "l"(a), "l"(b)); return r;
}
__device__ __forceinline__ ull add2(ull a, ull b) {
    ull r; asm("add.rn.f32x2 %0, %1, %2;" : "=l"(r) : "l"(a), "l"(b)); return r;
}
__device__ __forceinline__ float2 upk(ull v) {
    float2 r; asm("mov.b64 {%0,%1},%2;" : "=f"(r.x), "=f"(r.y) : "l"(v)); return r;
}
__device__ __forceinline__ unsigned ordkey(float s) {
    unsigned u = __float_as_uint(s);
    return (u & 0x80000000u) ? ~u : (u | 0x80000000u);
}

// ======================= K1: 128x128x16 GEMM, f32x2, conflict-free col split =======================
// Thread columns: {tx*4..+3} and {64+tx*4..+3}  (lane word-stride 4 -> no bank conflicts)
template<int MODE>
__global__ void __launch_bounds__(256) gemm128(const float* __restrict__ A,
                                               const float* __restrict__ W,
                                               const float* __restrict__ bias,
                                               float* __restrict__ out) {
    __shared__ float As[16][132];
    __shared__ float Bs[16][132];
    const int m0 = blockIdx.y * 128, n0 = blockIdx.x * 128;
    const int tid = threadIdx.x;
    const int tx = tid & 15, ty = tid >> 4;
    const float* Ap = (MODE == 1) ? g_ao : A;

    ull acc[8][4];
    #pragma unroll
    for (int r = 0; r < 8; r++)
        #pragma unroll
        for (int c = 0; c < 4; c++) acc[r][c] = 0ull;

    float4 pa[2], pb[2];
    #pragma unroll
    for (int i = 0; i < 2; i++) {
        int idx = tid + i * 256;
        int r = idx >> 2, kq = (idx & 3) * 4;
        pa[i] = *(const float4*)(Ap + (size_t)(m0 + r) * 512 + kq);
        pb[i] = *(const float4*)(W  + (size_t)(n0 + r) * 512 + kq);
    }

    for (int k0 = 0; k0 < 512; k0 += 16) {
        #pragma unroll
        for (int i = 0; i < 2; i++) {
            int idx = tid + i * 256;
            int r = idx >> 2, kq = (idx & 3) * 4;
            As[kq+0][r] = pa[i].x; As[kq+1][r] = pa[i].y; As[kq+2][r] = pa[i].z; As[kq+3][r] = pa[i].w;
            Bs[kq+0][r] = pb[i].x; Bs[kq+1][r] = pb[i].y; Bs[kq+2][r] = pb[i].z; Bs[kq+3][r] = pb[i].w;
        }
        __syncthreads();
        if (k0 + 16 < 512) {
            #pragma unroll
            for (int i = 0; i < 2; i++) {
                int idx = tid + i * 256;
                int r = idx >> 2, kq = (idx & 3) * 4;
                pa[i] = *(const float4*)(Ap + (size_t)(m0 + r) * 512 + k0 + 16 + kq);
                pb[i] = *(const float4*)(W  + (size_t)(n0 + r) * 512 + k0 + 16 + kq);
            }
        }
        #pragma unroll
        for (int kk = 0; kk < 16; kk++) {
            float4 ba = *(const float4*)&Bs[kk][tx * 4];
            float4 bb = *(const float4*)&Bs[kk][64 + tx * 4];
            ull kp0 = pk2(ba.x, ba.y), kp1 = pk2(ba.z, ba.w);
            ull kp2 = pk2(bb.x, bb.y), kp3 = pk2(bb.z, bb.w);
            float4 av0 = *(const float4*)&As[kk][ty * 8];
            float4 av1 = *(const float4*)&As[kk][ty * 8 + 4];
            float am[8] = {av0.x, av0.y, av0.z, av0.w, av1.x, av1.y, av1.z, av1.w};
            #pragma unroll
            for (int r = 0; r < 8; r++) {
                ull ab = pk2(am[r], am[r]);
                fma2(acc[r][0], ab, kp0); fma2(acc[r][1], ab, kp1);
                fma2(acc[r][2], ab, kp2); fma2(acc[r][3], ab, kp3);
            }
        }
        __syncthreads();
    }

    #pragma unroll
    for (int r = 0; r < 8; r++) {
        int m = m0 + ty * 8 + r;
        #pragma unroll
        for (int c = 0; c < 4; c++) {
            int n = n0 + ((c < 2) ? (tx * 4 + 2 * c) : (64 + tx * 4 + 2 * (c - 2)));
            if (MODE == 0) {
                int b = m >> 10, i = m & 1023;
                float2 v = upk(acc[r][c]);
                if (n < 512) {
                    int h = n >> 6, d = n & 63;
                    float* p = g_q + (((size_t)(b * 8 + h) << 10) + i) * 64 + d;
                    p[0] = v.x; p[1] = v.y;
                } else if (n < 1024) {
                    int nn = n - 512, h = nn >> 6, d = nn & 63;
                    float* p = g_kt + ((size_t)(b * 8 + h) * 64 + d) * 1024 + i;
                    p[0] = v.x; p[1024] = v.y;
                } else {
                    int nn = n - 1024, h = nn >> 6, d = nn & 63;
                    float* p = g_v + (((size_t)(b * 8 + h) << 10) + i) * 64 + d;
                    p[0] = v.x; p[1] = v.y;
                }
            } else {
                ull bv = *(const ull*)(bias + n);
                *(ull*)(out + (size_t)m * 512 + n) = add2(acc[r][c], bv);
            }
        }
    }
}

// ======================= K2: pooling + selector =======================
__global__ void __launch_bounds__(512) pool_kernel(const float* __restrict__ x) {
    const int b = blockIdx.x >> 3, s = blockIdx.x & 7;
    const int tid = threadIdx.x;
    const float* xb = x + ((size_t)b * 1024 + s * 128) * 512;
    float sum = 0.f;
    #pragma unroll 4
    for (int i = 0; i < 128; i++) sum += xb[(size_t)i * 512 + tid];
    g_part[(b * 8 + s) * 512 + tid] = sum;
}

__global__ void __launch_bounds__(512) selector(const float* __restrict__ W1,
                                                const float* __restrict__ b1,
                                                const float* __restrict__ W2,
                                                const float* __restrict__ b2,
                                                const float* __restrict__ logtau) {
    __shared__ float pooled[512];
    __shared__ float hh[256];
    __shared__ float lg[3];
    const int b = blockIdx.x, tid = threadIdx.x;
    {
        float s = 0.f;
        #pragma unroll
        for (int p = 0; p < 8; p++) s += g_part[(b * 8 + p) * 512 + tid];
        pooled[tid] = s * (1.0f / 1024.0f);
    }
    __syncthreads();
    if (tid < 256) {
        float a = b1[tid];
        const float* wr = W1 + (size_t)tid * 512;
        #pragma unroll 4
        for (int d = 0; d < 512; d++) a = fmaf(pooled[d], wr[d], a);
        hh[tid] = a > 0.f ? a : 0.f;
    }
    __syncthreads();
    if (tid < 3) {
        float a = b2[tid];
        const float* wr = W2 + (size_t)tid * 256;
        for (int d = 0; d < 256; d++) a = fmaf(hh[d], wr[d], a);
        lg[tid] = a;
    }
    __syncthreads();
    if (tid == 0) {
        float tau = expf(logtau[0]);
        tau = fminf(fmaxf(tau, 1e-4f), 10.0f);
        float l0 = lg[0] / tau, l1 = lg[1] / tau, l2 = lg[2] / tau;
        float mx = fmaxf(l0, fmaxf(l1, l2));
        float e0 = expf(l0 - mx), e1 = expf(l1 - mx), e2 = expf(l2 - mx);
        float inv = 1.0f / (e0 + e1 + e2);
        g_pw[b * 3 + 0] = e0 * inv;
        g_pw[b * 3 + 1] = e1 * inv;
        g_pw[b * 3 + 2] = e2 * inv;
    }
}

// ======================= K3: fused attention (32 rows / block, 512 threads) =======================
struct SmemAttn {
    float qT[64][36];             // 9.2 KB, row 144B (16B-aligned)
    float sc[32][1024];           // 128 KB
    union {
        float kbuf[2][8][1024];                                  // 64 KB, double-buffered K
        struct { float vbuf[2][64][64]; ull red[128][4][8]; } av; // 32 + 32 KB
        unsigned hist[16][256];                                  // 16 KB
    } u;
    unsigned thr[32];
    float    rowmax[32];
    float    rowsum[32];
    int      anyf[32];
};

__global__ void __launch_bounds__(512) attn_kernel(const int* __restrict__ mask,
                                                   const float* __restrict__ sparse_w,
                                                   const float* __restrict__ sparse_b) {
    extern __shared__ char smraw[];
    SmemAttn* sm = (SmemAttn*)smraw;
    const int tid = threadIdx.x;
    const int i0 = blockIdx.x * 32;
    const int h  = blockIdx.y;
    const int b  = blockIdx.z;
    const int bh = b * 8 + h;
    const float* qg  = g_q  + (size_t)bh * 1024 * 64;
    const float* ktg = g_kt + (size_t)bh * 64 * 1024;
    const float* vg  = g_v  + (size_t)bh * 1024 * 64;

    const float pw0 = g_pw[b * 3 + 0], pw1 = g_pw[b * 3 + 1], pw2 = g_pw[b * 3 + 2];
    const float wsp = sparse_w[h], bsp = sparse_b[h];
    const bool need_smask = (((pw1 > 0.05f) != (pw1 + pw2 > 0.05f)) ||
                             ((pw0 + pw1 > 0.05f) != (pw0 + pw1 + pw2 > 0.05f)));

    // ---- load qT (transposed q tile) ----
    #pragma unroll
    for (int it = 0; it < 4; it++) {
        int idx = tid + it * 512;          // 0..2047
        int r = idx >> 6, d = idx & 63;
        sm->qT[d][r] = qg[(size_t)(i0 + r) * 64 + d];
    }

    // ---- phase 1: scores, 8 rows x (4+4 split cols), f32x2, double-buffered K ----
    const int rg = tid >> 7;     // 0..3 -> rows rg*8..+8
    const int cg = tid & 127;    // cols cg*4 and 512+cg*4
    ull acc[8][4];
    #pragma unroll
    for (int r = 0; r < 8; r++)
        #pragma unroll
        for (int c = 0; c < 4; c++) acc[r][c] = 0ull;

    float4 kreg[4];
    #pragma unroll
    for (int it = 0; it < 4; it++) {
        int idx = tid + it * 512;
        int d = idx >> 8, jf = (idx & 255) * 4;
        kreg[it] = *(const float4*)(ktg + (size_t)d * 1024 + jf);
    }
    #pragma unroll
    for (int it = 0; it < 4; it++) {
        int idx = tid + it * 512;
        int d = idx >> 8, jf = (idx & 255) * 4;
        *(float4*)&sm->u.kbuf[0][d][jf] = kreg[it];
    }
    __syncthreads();

    for (int c = 0; c < 8; c++) {
        if (c < 7) {
            #pragma unroll
            for (int it = 0; it < 4; it++) {
                int idx = tid + it * 512;
                int d = idx >> 8, jf = (idx & 255) * 4;
                kreg[it] = *(const float4*)(ktg + (size_t)((c + 1) * 8 + d) * 1024 + jf);
            }
        }
        const float (*kb)[1024] = sm->u.kbuf[c & 1];
        #pragma unroll
        for (int dd = 0; dd < 8; dd++) {
            int d = c * 8 + dd;
            float4 ka = *(const float4*)&kb[dd][cg * 4];
            float4 kc = *(const float4*)&kb[dd][512 + cg * 4];
            ull kp0 = pk2(ka.x, ka.y), kp1 = pk2(ka.z, ka.w);
            ull kp2 = pk2(kc.x, kc.y), kp3 = pk2(kc.z, kc.w);
            float4 qv0 = *(const float4*)&sm->qT[d][rg * 8];
            float4 qv1 = *(const float4*)&sm->qT[d][rg * 8 + 4];
            float qs[8] = {qv0.x, qv0.y, qv0.z, qv0.w, qv1.x, qv1.y, qv1.z, qv1.w};
            #pragma unroll
            for (int r = 0; r < 8; r++) {
                ull qb = pk2(qs[r], qs[r]);
                fma2(acc[r][0], qb, kp0); fma2(acc[r][1], qb, kp1);
                fma2(acc[r][2], qb, kp2); fma2(acc[r][3], qb, kp3);
            }
        }
        if (c < 7) {
            __syncthreads();
            #pragma unroll
            for (int it = 0; it < 4; it++) {
                int idx = tid + it * 512;
                int d = idx >> 8, jf = (idx & 255) * 4;
                *(float4*)&sm->u.kbuf[(c + 1) & 1][d][jf] = kreg[it];
            }
            __syncthreads();
        }
    }
    {
        const ull sc2 = pk2(0.125f, 0.125f);
        #pragma unroll
        for (int r = 0; r < 8; r++) {
            ulonglong2 sa; sa.x = mul2(acc[r][0], sc2); sa.y = mul2(acc[r][1], sc2);
            *(ulonglong2*)&sm->sc[rg * 8 + r][cg * 4] = sa;
            ulonglong2 sb; sb.x = mul2(acc[r][2], sc2); sb.y = mul2(acc[r][3], sc2);
            *(ulonglong2*)&sm->sc[rg * 8 + r][512 + cg * 4] = sb;
        }
    }
    __syncthreads();

    // ---- phase 2: exact kth-largest per row (radix select), 16 warps x 2 rows ----
    if (need_smask) {
        const int wq = tid >> 5, lane = tid & 31;
        for (int rr = 0; rr < 2; rr++) {
            const int r = wq * 2 + rr;
            unsigned prefix = 0;
            int kneed = KNEED;
            #pragma unroll
            for (int pass = 0; pass < 4; pass++) {
                const int shift = 24 - 8 * pass;
                #pragma unroll
                for (int q = 0; q < 8; q++) sm->u.hist[wq][lane * 8 + q] = 0u;
                __syncwarp();
                for (int t = 0; t < 32; t++) {
                    int j = lane + t * 32;
                    float s = fmaf(sm->sc[r][j], wsp, bsp);
                    unsigned u = ordkey(s);
                    bool cand;
                    if (pass == 0) cand = true;
                    else           cand = (((u ^ prefix) >> (shift + 8)) == 0u);
                    int bucket = cand ? (int)((u >> shift) & 255u) : 256;
                    unsigned mm = __match_any_sync(0xffffffffu, bucket);
                    if ((__ffs(mm) - 1) == lane && bucket < 256)
                        atomicAdd(&sm->u.hist[wq][bucket], (unsigned)__popc(mm));
                }
                __syncwarp();
                const int base = 255 - lane * 8;
                int c[8]; int loc = 0;
                #pragma unroll
                for (int q = 0; q < 8; q++) { c[q] = (int)sm->u.hist[wq][base - q]; loc += c[q]; }
                int pre = loc;
                #pragma unroll
                for (int o = 1; o < 32; o <<= 1) {
                    int v = __shfl_up_sync(0xffffffffu, pre, o);
                    if (lane >= o) pre += v;
                }
                const int excl = pre - loc;
                const bool hit = (excl < kneed) && (kneed <= pre);
                const unsigned hb = __ballot_sync(0xffffffffu, hit);
                const int hl = __ffs(hb) - 1;
                int bsel = 0, kn2 = 0;
                if (hit) {
                    int rem = kneed - excl;
                    #pragma unroll
                    for (int q = 0; q < 8; q++) {
                        if (rem <= c[q]) { bsel = base - q; kn2 = rem; break; }
                        rem -= c[q];
                    }
                }
                bsel = __shfl_sync(0xffffffffu, bsel, hl);
                kn2  = __shfl_sync(0xffffffffu, kn2,  hl);
                prefix |= ((unsigned)bsel) << shift;
                kneed = kn2;
                __syncwarp();
            }
            if (lane == 0) sm->thr[r] = prefix;
        }
    } else {
        if (tid < 32) sm->thr[tid] = 0u;
    }
    __syncthreads();

    // ---- phase 3: combined mask + fallback + softmax ----
    const int r3 = tid >> 4;   // 0..31
    const int c3 = tid & 15;
    {
        const int* mrow = mask + b * 1024;
        const unsigned thrv = sm->thr[r3];
        const int ii = i0 + r3;
        float locmax = -3.0e38f;
        int any = 0;
        for (int t = 0; t < 64; t++) {
            int j = c3 + t * 16;
            float f = sm->sc[r3][j];
            float s = fmaf(f, wsp, bsp);
            float smv = (ordkey(s) >= thrv) ? 1.0f : 0.0f;
            float lcl = (j >= ii - 16 && j <= ii + 16) ? 1.0f : 0.0f;
            float comb = fmaf(pw0, lcl, fmaf(pw2, smv, pw1));
            bool keep = (comb > 0.05f) && (mrow[j] != 0);
            float val = keep ? f : NEGV;
            sm->sc[r3][j] = val;
            if (keep) { locmax = fmaxf(locmax, f); any = 1; }
        }
        #pragma unroll
        for (int o = 8; o; o >>= 1) {
            locmax = fmaxf(locmax, __shfl_down_sync(0xffffffffu, locmax, o, 16));
            any   |= __shfl_down_sync(0xffffffffu, any, o, 16);
        }
        if (c3 == 0) { sm->rowmax[r3] = locmax; sm->anyf[r3] = any; }
    }
    __syncthreads();
    if (tid < 32) {
        if (!sm->anyf[tid]) { sm->sc[tid][0] = 0.0f; sm->rowmax[tid] = 0.0f; }
    }
    __syncthreads();
    {
        const float rmax = sm->rowmax[r3];
        float lsum = 0.f;
        for (int t = 0; t < 64; t++) {
            int j = c3 + t * 16;
            float e = __expf(sm->sc[r3][j] - rmax);
            sm->sc[r3][j] = e;
            lsum += e;
        }
        #pragma unroll
        for (int o = 8; o; o >>= 1)
            lsum += __shfl_down_sync(0xffffffffu, lsum, o, 16);
        if (c3 == 0) sm->rowsum[r3] = lsum;
    }
    __syncthreads();

    // ---- phase 4: AV, all 512 threads: 4 rows x 4 cols x 4-way j-split ----
    const int cgrp = tid & 15;          // cols cgrp*4..+3
    const int rgrp = (tid >> 4) & 7;    // rows rgrp*4..+4
    const int jh   = tid >> 7;          // 0..3 j-slice
    ull a4[4][2];
    #pragma unroll
    for (int r = 0; r < 4; r++) { a4[r][0] = 0ull; a4[r][1] = 0ull; }

    float4 vreg[2];
    #pragma unroll
    for (int it = 0; it < 2; it++) {
        int idx = tid + it * 512;             // 0..1023 float4 slots of 64x64 tile
        int jj = idx >> 4, df = (idx & 15) * 4;
        vreg[it] = *(const float4*)(vg + (size_t)jj * 64 + df);
    }
    #pragma unroll
    for (int it = 0; it < 2; it++) {
        int idx = tid + it * 512;
        int jj = idx >> 4, df = (idx & 15) * 4;
        *(float4*)&sm->u.av.vbuf[0][jj][df] = vreg[it];
    }
    __syncthreads();

    for (int c = 0; c < 16; c++) {
        if (c < 15) {
            #pragma unroll
            for (int it = 0; it < 2; it++) {
                int idx = tid + it * 512;
                int jj = idx >> 4, df = (idx & 15) * 4;
                vreg[it] = *(const float4*)(vg + (size_t)((c + 1) * 64 + jj) * 64 + df);
            }
        }
        const float (*vb)[64] = sm->u.av.vbuf[c & 1];
        #pragma unroll
        for (int q = 0; q < 4; q++) {          // 4 quads of 4 j
            const int jl = jh * 16 + q * 4;    // local j within 64-chunk
            const int j  = c * 64 + jl;
            float4 pv[4];
            #pragma unroll
            for (int r = 0; r < 4; r++)
                pv[r] = *(const float4*)&sm->sc[rgrp * 4 + r][j];
            #pragma unroll
            for (int t = 0; t < 4; t++) {
                float4 vv = *(const float4*)&vb[jl + t][cgrp * 4];
                ull v0 = pk2(vv.x, vv.y), v1 = pk2(vv.z, vv.w);
                float pt[4] = { t==0?pv[0].x:t==1?pv[0].y:t==2?pv[0].z:pv[0].w,
                                t==0?pv[1].x:t==1?pv[1].y:t==2?pv[1].z:pv[1].w,
                                t==0?pv[2].x:t==1?pv[2].y:t==2?pv[2].z:pv[2].w,
                                t==0?pv[3].x:t==1?pv[3].y:t==2?pv[3].z:pv[3].w };
                #pragma unroll
                for (int r = 0; r < 4; r++) {
                    ull pb = pk2(pt[r], pt[r]);
                    fma2(a4[r][0], pb, v0);
                    fma2(a4[r][1], pb, v1);
                }
            }
        }
        if (c < 15) {
            __syncthreads();
            #pragma unroll
            for (int it = 0; it < 2; it++) {
                int idx = tid + it * 512;
                int jj = idx >> 4, df = (idx & 15) * 4;
                *(float4*)&sm->u.av.vbuf[(c + 1) & 1][jj][df] = vreg[it];
            }
            __syncthreads();
        }
    }
    // j-split reduction via smem
    __syncthreads();
    #pragma unroll
    for (int r = 0; r < 4; r++) {
        sm->u.av.red[rgrp * 16 + cgrp][jh][r * 2 + 0] = a4[r][0];
        sm->u.av.red[rgrp * 16 + cgrp][jh][r * 2 + 1] = a4[r][1];
    }
    __syncthreads();
    #pragma unroll
    for (int oo = 0; oo < 2; oo++) {
        int o = tid + oo * 512;        // 0..1023 output ull (32 rows x 32 col-pairs)
        int row = o >> 5, cp = o & 31;
        int rgo = row >> 2, rro = row & 3, cgo = cp >> 1, uo = cp & 1;
        ull s = sm->u.av.red[rgo * 16 + cgo][0][rro * 2 + uo];
        s = add2(s, sm->u.av.red[rgo * 16 + cgo][1][rro * 2 + uo]);
        s = add2(s, sm->u.av.red[rgo * 16 + cgo][2][rro * 2 + uo]);
        s = add2(s, sm->u.av.red[rgo * 16 + cgo][3][rro * 2 + uo]);
        float inv = 1.0f / sm->rowsum[row];
        float2 f = upk(s);
        float* op = g_ao + ((size_t)(b * 1024 + i0 + row)) * 512 + h * 64 + cgo * 4 + uo * 2;
        op[0] = f.x * inv; op[1] = f.y * inv;
    }
}

// ======================= launch =======================
extern "C" void kernel_launch(void* const* d_in, const int* in_sizes, int n_in,
                              void* d_out, int out_size) {
    const float* x      = (const float*)d_in[0];
    const int*   mask   = (const int*)  d_in[1];
    const float* Wqkv   = (const float*)d_in[2];
    const float* Wproj  = (const float*)d_in[3];
    const float* bproj  = (const float*)d_in[4];
    const float* Wsel1  = (const float*)d_in[5];
    const float* bsel1  = (const float*)d_in[6];
    const float* Wsel2  = (const float*)d_in[7];
    const float* bsel2  = (const float*)d_in[8];
    const float* logtau = (const float*)d_in[9];
    const float* sw     = (const float*)d_in[10];
    const float* sb     = (const float*)d_in[11];
    float* out = (float*)d_out;

    static int smem_set = 0;
    if (!smem_set) {
        cudaFuncSetAttribute(attn_kernel, cudaFuncAttributeMaxDynamicSharedMemorySize,
                             (int)sizeof(SmemAttn));
        smem_set = 1;
    }

    gemm128<0><<<dim3(12, 32), 256>>>(x, Wqkv, nullptr, nullptr);
    pool_kernel<<<32, 512>>>(x);
    selector<<<4, 512>>>(Wsel1, bsel1, Wsel2, bsel2, logtau);
    attn_kernel<<<dim3(32, 8, 4), 512, sizeof(SmemAttn)>>>(mask, sw, sb);
    gemm128<1><<<dim3(4, 32), 256>>>(nullptr, Wproj, bproj, out);
}